// round 6
// baseline (speedup 1.0000x reference)
#include <cuda_runtime.h>
#include <cuda_bf16.h>
#include <cstdint>

// Problem constants: x(4,256,64,64), p_w(18,256,3,3), p_b(18), conv_w(256,256,3,3)
// out(4,256,64,64). K=3, stride=1, pad=1. Hp=Wp=66.

#define NB   4
#define NC   256
#define NH   64
#define NW   64
#define NCO  256
#define KTOT 2304   // 256*9

// Scratch (device globals; allocation-free per harness rules)
__device__ float g_off[NB * 18 * NH * NW];                 // predicted offsets (B,18,H,W)
__device__ __align__(16) float g_wt[KTOT * NCO];           // conv_w transposed to [k][o]

// ---------------------------------------------------------------------------
// Kernel 0: transpose conv_w (O,C,3,3)=[o][k] -> g_wt[k][o]
// ---------------------------------------------------------------------------
__global__ void k_transpose(const float* __restrict__ w) {
    int e = blockIdx.x * 256 + threadIdx.x;
    int o = e / KTOT;
    int k = e - o * KTOT;
    g_wt[k * NCO + o] = w[e];
}

// ---------------------------------------------------------------------------
// Kernel 1: offset conv  (B,18,H,W) = conv3x3(x, p_w, pad=1) + p_b
// ---------------------------------------------------------------------------
__global__ void __launch_bounds__(256) k_offset(const float* __restrict__ x,
                                                const float* __restrict__ pw,
                                                const float* __restrict__ pb) {
    __shared__ __align__(16) float patch[4][3][68];
    __shared__ __align__(16) float ws[4][9][20];
    __shared__ float red[4][64][18];

    int b = blockIdx.x >> 6;
    int h = blockIdx.x & 63;
    int tid = threadIdx.x;
    int g   = tid >> 6;
    int pix = tid & 63;

    float acc[20];
#pragma unroll
    for (int i = 0; i < 20; i++) acc[i] = 0.f;

    const float* xb = x + ((size_t)b << 20);

    for (int cc = 0; cc < 64; cc++) {
        for (int l = tid; l < 4 * 3 * 66; l += 256) {
            int gg  = l / 198;
            int rem = l - gg * 198;
            int r   = rem / 66;
            int wc  = rem - r * 66;
            int y   = h + r - 1;
            int xw  = wc - 1;
            float v = 0.f;
            if (y >= 0 && y < NH && xw >= 0 && xw < NW)
                v = xb[((gg * 64 + cc) << 12) + (y << 6) + xw];
            patch[gg][r][wc] = v;
        }
        for (int l = tid; l < 720; l += 256) {
            int gg  = l / 180;
            int rem = l - gg * 180;
            int n   = rem / 20;
            int oc  = rem - n * 20;
            float v = 0.f;
            if (oc < 18) v = pw[oc * KTOT + (gg * 64 + cc) * 9 + n];
            ws[gg][n][oc] = v;
        }
        __syncthreads();

#pragma unroll
        for (int ky = 0; ky < 3; ky++) {
#pragma unroll
            for (int kx = 0; kx < 3; kx++) {
                float s = patch[g][ky][pix + kx];
                int n = ky * 3 + kx;
#pragma unroll
                for (int q = 0; q < 5; q++) {
                    float4 w4 = *(const float4*)&ws[g][n][q * 4];
                    acc[q * 4 + 0] += w4.x * s;
                    acc[q * 4 + 1] += w4.y * s;
                    acc[q * 4 + 2] += w4.z * s;
                    acc[q * 4 + 3] += w4.w * s;
                }
            }
        }
        __syncthreads();
    }

#pragma unroll
    for (int i = 0; i < 18; i++) red[g][pix][i] = acc[i];
    __syncthreads();

    for (int e = tid; e < 64 * 18; e += 256) {
        int p2 = e / 18;
        int oc = e - p2 * 18;
        float v = red[0][p2][oc] + red[1][p2][oc] + red[2][p2][oc] + red[3][p2][oc] + pb[oc];
        g_off[((b * 18 + oc) << 12) + (h << 6) + p2] = v;
    }
}

// ---------------------------------------------------------------------------
// Kernel 2: fused bilinear sampling + implicit GEMM (packed f32x2 FFMA2 path)
// Tile: 256 oc x 128 pixels (2 rows), 512 threads, grid = 128
// ---------------------------------------------------------------------------
__device__ __forceinline__ void cp16(void* smem_dst, const void* gsrc) {
    uint32_t s = (uint32_t)__cvta_generic_to_shared(smem_dst);
    asm volatile("cp.async.cg.shared.global [%0], [%1], 16;" ::"r"(s), "l"(gsrc));
}
__device__ __forceinline__ void cp_commit() { asm volatile("cp.async.commit_group;"); }
__device__ __forceinline__ void cp_wait1()  { asm volatile("cp.async.wait_group 1;"); }
__device__ __forceinline__ void cp_wait0()  { asm volatile("cp.async.wait_group 0;"); }

// packed fp32x2 helpers (Blackwell FFMA2 — only reachable via PTX)
__device__ __forceinline__ unsigned long long pk2(float a, float b) {
    unsigned long long r;
    asm("mov.b64 %0, {%1, %2};" : "=l"(r) : "f"(a), "f"(b));
    return r;
}
__device__ __forceinline__ void fma2(unsigned long long& d, unsigned long long a,
                                     unsigned long long b) {
    asm("fma.rn.f32x2 %0, %1, %2, %0;" : "+l"(d) : "l"(a), "l"(b));
}

// One k-chunk = 36 k-rows x 128 pixels = 4608 S elements (512 threads x 9)
__device__ __forceinline__ void produce_S(float* Sd, const float* __restrict__ xb,
                                          const int* idxs, const float* wgts,
                                          int c0, int tid) {
#pragma unroll
    for (int i = 0; i < 9; i++) {
        int e2  = tid + (i << 9);      // 0..4607
        int k   = e2 >> 7;             // 0..35
        int pix = e2 & 127;
        int ci  = k / 9;
        int n   = k - ci * 9;
        const float* xp = xb + ((c0 + ci) << 12);
        int te = (pix * 9 + n) << 2;
        int4   id = *(const int4*)(idxs + te);
        float4 wg = *(const float4*)(wgts + te);
        Sd[(k << 7) + pix] = wg.x * xp[id.x] + wg.y * xp[id.y] +
                             wg.z * xp[id.z] + wg.w * xp[id.w];
    }
}

__device__ __forceinline__ void load_W_chunk(float* Wn, const float* gsrc, int tid) {
    const float4* src = (const float4*)gsrc;
    float4* dst = (float4*)Wn;
#pragma unroll
    for (int i = 0; i < 4; i++) {
        int e2 = tid + (i << 9);       // 0..2047
        cp16(dst + e2, src + e2);
    }
    if (tid < 256) cp16(dst + 2048 + tid, src + 2048 + tid);   // 2048..2303
}

__global__ void __launch_bounds__(512) k_main(const float* __restrict__ x,
                                              float* __restrict__ out) {
    extern __shared__ __align__(16) char smem_raw[];
    float* Ws   = (float*)smem_raw;           // [2][36][256]  73728 B
    float* Ss   = Ws + 2 * 36 * 256;          // [2][36][128]  36864 B
    int*   idxs = (int*)(Ss + 2 * 36 * 128);  // [1152][4]     18432 B
    float* wgts = (float*)(idxs + 1152 * 4);  // [1152][4]     18432 B

    int b   = blockIdx.x >> 5;        // batch
    int r2  = blockIdx.x & 31;        // row-pair
    int h0  = r2 * 2;
    int tid = threadIdx.x;
    const float* xb = x + ((size_t)b << 20);

    // ---- per-block bilinear tables: 128 pixels x 9 taps, 4 corners each ----
    for (int e = tid; e < 1152; e += 512) {
        int pix = e / 9;
        int n   = e - pix * 9;
        int h   = h0 + (pix >> 6);
        int w   = pix & 63;
        int gbase = ((b * 18 + n) << 12) + (h << 6) + w;
        float offy = g_off[gbase];
        float offx = g_off[gbase + (9 << 12)];
        int ky = n / 3;
        int kx = n - ky * 3;
        float py = (float)(h + ky) + offy;     // padded-image coords
        float px = (float)(w + kx) + offx;
        float fy = floorf(py), fx = floorf(px);
        float qlty = fminf(fmaxf(fy, 0.f), 65.f);
        float qrby = fminf(fmaxf(fy + 1.f, 0.f), 65.f);
        float qltx = fminf(fmaxf(fx, 0.f), 65.f);
        float qrbx = fminf(fmaxf(fx + 1.f, 0.f), 65.f);
        float pyc = fminf(fmaxf(py, 0.f), 65.f);
        float pxc = fminf(fmaxf(px, 0.f), 65.f);
        float dly = 1.f + qlty - pyc, dry = 1.f - qrby + pyc;
        float dlx = 1.f + qltx - pxc, drx = 1.f - qrbx + pxc;
        int ily = (int)qlty, iry = (int)qrby, ilx = (int)qltx, irx = (int)qrbx;
        bool vly = (ily >= 1) && (ily <= 64), vry = (iry >= 1) && (iry <= 64);
        bool vlx = (ilx >= 1) && (ilx <= 64), vrx = (irx >= 1) && (irx <= 64);
        int bly = (ily - 1) << 6, bry = (iry - 1) << 6;
        int   i0 = (vly && vlx) ? bly + ilx - 1 : 0;
        float w0 = (vly && vlx) ? dly * dlx : 0.f;
        int   i1 = (vry && vrx) ? bry + irx - 1 : 0;
        float w1 = (vry && vrx) ? dry * drx : 0.f;
        int   i2 = (vly && vrx) ? bly + irx - 1 : 0;
        float w2 = (vly && vrx) ? dly * drx : 0.f;
        int   i3 = (vry && vlx) ? bry + ilx - 1 : 0;
        float w3 = (vry && vlx) ? dry * dlx : 0.f;
        *(int4*)(idxs + e * 4)   = make_int4(i0, i1, i2, i3);
        *(float4*)(wgts + e * 4) = make_float4(w0, w1, w2, w3);
    }
    __syncthreads();

    // ---- prologue: S chunk0 + async W chunk0 ----
    produce_S(Ss, xb, idxs, wgts, 0, tid);
    load_W_chunk(Ws, g_wt, tid);
    cp_commit();

    unsigned long long acc2[8][4];   // [oc][pixel-pair], packed f32x2
#pragma unroll
    for (int o = 0; o < 8; o++)
#pragma unroll
        for (int q = 0; q < 4; q++) acc2[o][q] = 0ULL;

    int og = tid >> 4;   // 0..31 -> 8 output channels each
    int pg = tid & 15;   // 0..15 -> 8 pixels each

    for (int ch = 0; ch < 64; ch++) {
        int cur = ch & 1;
        float* Wc = Ws + cur * 9216;
        float* Sc = Ss + cur * 4608;
        float* Wn = Ws + (cur ^ 1) * 9216;
        float* Sn = Ss + (cur ^ 1) * 4608;

        __syncthreads();   // everyone done reading the 'next' buffers from ch-1
        if (ch + 1 < 64) {
            load_W_chunk(Wn, g_wt + (size_t)(ch + 1) * 36 * 256, tid);
            cp_commit();
            cp_wait1();    // current chunk's W has landed
        } else {
            cp_wait0();
        }
        __syncthreads();   // all threads' W(cur) visible; S(cur) produced last iter

        // ---- issue next-S gathers FIRST so LDG latency hides under the GEMM ----
        if (ch + 1 < 64)
            produce_S(Sn, xb, idxs, wgts, (ch + 1) * 4, tid);

        // ---- GEMM: 36 k-steps, 8x8 register tile via packed FFMA2 ----
#pragma unroll 4
        for (int k = 0; k < 36; k++) {
            float4 wA = *(const float4*)(Wc + (k << 8) + og * 8);
            float4 wB = *(const float4*)(Wc + (k << 8) + og * 8 + 4);
            // S pixel pairs load directly as packed 64-bit lanes
            ulonglong2 sA = *(const ulonglong2*)(Sc + (k << 7) + pg * 8);
            ulonglong2 sB = *(const ulonglong2*)(Sc + (k << 7) + pg * 8 + 4);
            unsigned long long sp0 = sA.x, sp1 = sA.y, sp2 = sB.x, sp3 = sB.y;
            float wv[8] = {wA.x, wA.y, wA.z, wA.w, wB.x, wB.y, wB.z, wB.w};
#pragma unroll
            for (int o = 0; o < 8; o++) {
                unsigned long long wp = pk2(wv[o], wv[o]);
                fma2(acc2[o][0], wp, sp0);
                fma2(acc2[o][1], wp, sp1);
                fma2(acc2[o][2], wp, sp2);
                fma2(acc2[o][3], wp, sp3);
            }
        }
    }

    // ---- store: out(b, oc, h, w); pixels pg*8..pg*8+7 lie in one row ----
    int h = h0 + (pg >> 3);
    int wb = (pg & 7) * 8;
    float* ob = out + ((size_t)b << 20) + (h << 6) + wb;
#pragma unroll
    for (int o = 0; o < 8; o++) {
        float2 p0 = *(float2*)&acc2[o][0];
        float2 p1 = *(float2*)&acc2[o][1];
        float2 p2 = *(float2*)&acc2[o][2];
        float2 p3 = *(float2*)&acc2[o][3];
        float* p = ob + ((og * 8 + o) << 12);
        *(float4*)p       = make_float4(p0.x, p0.y, p1.x, p1.y);
        *(float4*)(p + 4) = make_float4(p2.x, p2.y, p3.x, p3.y);
    }
}

// ---------------------------------------------------------------------------
extern "C" void kernel_launch(void* const* d_in, const int* in_sizes, int n_in,
                              void* d_out, int out_size) {
    const float* x  = (const float*)d_in[0];   // (4,256,64,64)
    const float* pw = (const float*)d_in[1];   // (18,256,3,3)
    const float* pb = (const float*)d_in[2];   // (18,)
    const float* cw = (const float*)d_in[3];   // (256,256,3,3)
    float* out = (float*)d_out;

    cudaFuncSetAttribute(k_main, cudaFuncAttributeMaxDynamicSharedMemorySize, 147456);

    k_transpose<<<KTOT * NCO / 256, 256>>>(cw);
    k_offset<<<NB * NH, 256>>>(x, pw, pb);
    k_main<<<128, 512, 147456>>>(x, out);
}

// round 9
// speedup vs baseline: 1.5613x; 1.5613x over previous
#include <cuda_runtime.h>
#include <cuda_bf16.h>
#include <cstdint>

// x(4,256,64,64), p_w(18,256,3,3), p_b(18), conv_w(256,256,3,3) -> out(4,256,64,64)
#define NB   4
#define NH   64
#define NW   64
#define KTOT 2304   // 256*9

__device__ float g_off[NB * 18 * NH * NW];
__device__ __align__(16) __nv_bfloat16 g_whi[256 * KTOT];  // [oc][k] bf16 hi
__device__ __align__(16) __nv_bfloat16 g_wlo[256 * KTOT];  // [oc][k] bf16 lo

// ---------------------------------------------------------------------------
// Kernel 0: split conv_w into bf16 hi/lo, layout [oc][k]
// ---------------------------------------------------------------------------
__global__ void k_prep(const float* __restrict__ w) {
    int e = blockIdx.x * 256 + threadIdx.x;    // 589824 exact
    float v = w[e];
    __nv_bfloat16 h = __float2bfloat16(v);
    __nv_bfloat16 l = __float2bfloat16(v - __bfloat162float(h));
    g_whi[e] = h;
    g_wlo[e] = l;
}

// ---------------------------------------------------------------------------
// Kernel 1: offset conv (unchanged from passing version)
// ---------------------------------------------------------------------------
__global__ void __launch_bounds__(256) k_offset(const float* __restrict__ x,
                                                const float* __restrict__ pw,
                                                const float* __restrict__ pb) {
    __shared__ __align__(16) float patch[4][3][68];
    __shared__ __align__(16) float ws[4][9][20];
    __shared__ float red[4][64][18];

    int b = blockIdx.x >> 6;
    int h = blockIdx.x & 63;
    int tid = threadIdx.x;
    int g   = tid >> 6;
    int pix = tid & 63;

    float acc[20];
#pragma unroll
    for (int i = 0; i < 20; i++) acc[i] = 0.f;

    const float* xb = x + ((size_t)b << 20);

    for (int cc = 0; cc < 64; cc++) {
        for (int l = tid; l < 4 * 3 * 66; l += 256) {
            int gg  = l / 198;
            int rem = l - gg * 198;
            int r   = rem / 66;
            int wc  = rem - r * 66;
            int y   = h + r - 1;
            int xw  = wc - 1;
            float v = 0.f;
            if (y >= 0 && y < NH && xw >= 0 && xw < NW)
                v = xb[((gg * 64 + cc) << 12) + (y << 6) + xw];
            patch[gg][r][wc] = v;
        }
        for (int l = tid; l < 720; l += 256) {
            int gg  = l / 180;
            int rem = l - gg * 180;
            int n   = rem / 20;
            int oc  = rem - n * 20;
            float v = 0.f;
            if (oc < 18) v = pw[oc * KTOT + (gg * 64 + cc) * 9 + n];
            ws[gg][n][oc] = v;
        }
        __syncthreads();

#pragma unroll
        for (int ky = 0; ky < 3; ky++) {
#pragma unroll
            for (int kx = 0; kx < 3; kx++) {
                float s = patch[g][ky][pix + kx];
                int n = ky * 3 + kx;
#pragma unroll
                for (int q = 0; q < 5; q++) {
                    float4 w4 = *(const float4*)&ws[g][n][q * 4];
                    acc[q * 4 + 0] += w4.x * s;
                    acc[q * 4 + 1] += w4.y * s;
                    acc[q * 4 + 2] += w4.z * s;
                    acc[q * 4 + 3] += w4.w * s;
                }
            }
        }
        __syncthreads();
    }

#pragma unroll
    for (int i = 0; i < 18; i++) red[g][pix][i] = acc[i];
    __syncthreads();

    for (int e = tid; e < 64 * 18; e += 256) {
        int p2 = e / 18;
        int oc = e - p2 * 18;
        float v = red[0][p2][oc] + red[1][p2][oc] + red[2][p2][oc] + red[3][p2][oc] + pb[oc];
        g_off[((b * 18 + oc) << 12) + (h << 6) + p2] = v;
    }
}

// ---------------------------------------------------------------------------
// Kernel 2: warp-level bf16 mma.sync 3-pass implicit GEMM + fused sampling
// CTA: 256 oc x 128 px, 512 thr = 16 warps (4M x 4N), warp tile 64x32.
// K=2304 in 72 chunks of 32. smem rows padded to 80B (conflict-free ldmatrix).
// ---------------------------------------------------------------------------
#define OFF_TABI 0          // ushort4[1152]   9216 B
#define OFF_TABW 9216       // float4 [1152]  18432 B
#define OFF_W    27648      // 2 buf x (hi 20480 + lo 20480) = 81920
#define WBUF     40960
#define OFF_S    109568     // 2 buf x (hi 10240 + lo 10240) = 40960
#define SBUF     20480
#define SMEM_SZ  150528
#define RSTRIDE  80         // bytes per k-row (32 bf16 = 64B + 16B pad)

__device__ __forceinline__ void cp16(uint32_t smem_dst, const void* gsrc) {
    asm volatile("cp.async.cg.shared.global [%0], [%1], 16;" ::"r"(smem_dst), "l"(gsrc));
}
__device__ __forceinline__ void ldsm4(uint32_t a[4], uint32_t addr) {
    asm volatile("ldmatrix.sync.aligned.m8n8.x4.shared.b16 {%0,%1,%2,%3}, [%4];"
                 : "=r"(a[0]), "=r"(a[1]), "=r"(a[2]), "=r"(a[3]) : "r"(addr));
}
__device__ __forceinline__ void ldsm2(uint32_t a[2], uint32_t addr) {
    asm volatile("ldmatrix.sync.aligned.m8n8.x2.shared.b16 {%0,%1}, [%2];"
                 : "=r"(a[0]), "=r"(a[1]) : "r"(addr));
}
__device__ __forceinline__ void mma16816(float d[4], const uint32_t a[4], const uint32_t b[2]) {
    asm volatile(
        "mma.sync.aligned.m16n8k16.row.col.f32.bf16.bf16.f32 "
        "{%0,%1,%2,%3}, {%4,%5,%6,%7}, {%8,%9}, {%0,%1,%2,%3};"
        : "+f"(d[0]), "+f"(d[1]), "+f"(d[2]), "+f"(d[3])
        : "r"(a[0]), "r"(a[1]), "r"(a[2]), "r"(a[3]), "r"(b[0]), "r"(b[1]));
}

// load W chunk ch (32 k) into buffer: hi[256][80B] + lo[256][80B]
__device__ __forceinline__ void load_W(uint32_t wbase, int ch, int tid) {
#pragma unroll
    for (int j = 0; j < 4; j++) {
        int idx = tid + (j << 9);       // 0..2047
        int t   = idx >> 10;            // 0=hi, 1=lo
        int r10 = idx & 1023;
        int oc  = r10 >> 2;
        int c16 = r10 & 3;
        const __nv_bfloat16* gw = t ? g_wlo : g_whi;
        cp16(wbase + t * 20480 + oc * RSTRIDE + c16 * 16,
             gw + (size_t)oc * KTOT + ch * 32 + c16 * 8);
    }
}

// produce S chunk ch: hi[128][80B] + lo[128][80B], [pix][k] rows
__device__ __forceinline__ void produce_S(char* sbase, const float* __restrict__ xb,
                                          const ushort4* tabi, const float4* tabw,
                                          int ch, int tid) {
#pragma unroll
    for (int j = 0; j < 4; j++) {
        int idx = tid + (j << 9);       // 0..2047 (bf16 word-pairs)
        int kk2 = idx >> 7;             // 0..15
        int pix = idx & 127;
        uint32_t hbits = 0, lbits = 0;
#pragma unroll
        for (int u = 0; u < 2; u++) {
            int k  = ch * 32 + kk2 * 2 + u;
            int ci = k / 9;
            int n  = k - ci * 9;
            ushort4 id = tabi[pix * 9 + n];
            float4  wg = tabw[pix * 9 + n];
            const float* xp = xb + (ci << 12);
            float s = wg.x * xp[id.x] + wg.y * xp[id.y] + wg.z * xp[id.z] + wg.w * xp[id.w];
            __nv_bfloat16 h = __float2bfloat16(s);
            __nv_bfloat16 l = __float2bfloat16(s - __bfloat162float(h));
            hbits |= (uint32_t)__bfloat16_as_ushort(h) << (u * 16);
            lbits |= (uint32_t)__bfloat16_as_ushort(l) << (u * 16);
        }
        int off = pix * RSTRIDE + kk2 * 4;
        *(uint32_t*)(sbase + off)         = hbits;
        *(uint32_t*)(sbase + 10240 + off) = lbits;
    }
}

__global__ void __launch_bounds__(512, 1) k_main(const float* __restrict__ x,
                                                 float* __restrict__ out) {
    extern __shared__ __align__(16) char sm[];
    uint32_t smb = (uint32_t)__cvta_generic_to_shared(sm);
    int tid  = threadIdx.x;
    int wid  = tid >> 5;
    int lane = tid & 31;
    int wm   = wid >> 2;              // 0..3 -> oc base wm*64
    int wn   = wid & 3;               // 0..3 -> pix base wn*32
    int b    = blockIdx.x >> 5;
    int h0   = (blockIdx.x & 31) * 2;
    const float* xb = x + ((size_t)b << 20);

    ushort4* tabi = (ushort4*)(sm + OFF_TABI);
    float4*  tabw = (float4*)(sm + OFF_TABW);

    // ---- bilinear tables: 128 pixels x 9 taps ----
    for (int e = tid; e < 1152; e += 512) {
        int pix = e / 9;
        int n   = e - pix * 9;
        int h   = h0 + (pix >> 6);
        int w   = pix & 63;
        int gbase = ((b * 18 + n) << 12) + (h << 6) + w;
        float offy = g_off[gbase];
        float offx = g_off[gbase + (9 << 12)];
        int ky = n / 3;
        int kx = n - ky * 3;
        float py = (float)(h + ky) + offy;
        float px = (float)(w + kx) + offx;
        float fy = floorf(py), fx = floorf(px);
        float qlty = fminf(fmaxf(fy, 0.f), 65.f);
        float qrby = fminf(fmaxf(fy + 1.f, 0.f), 65.f);
        float qltx = fminf(fmaxf(fx, 0.f), 65.f);
        float qrbx = fminf(fmaxf(fx + 1.f, 0.f), 65.f);
        float pyc = fminf(fmaxf(py, 0.f), 65.f);
        float pxc = fminf(fmaxf(px, 0.f), 65.f);
        float dly = 1.f + qlty - pyc, dry = 1.f - qrby + pyc;
        float dlx = 1.f + qltx - pxc, drx = 1.f - qrbx + pxc;
        int ily = (int)qlty, iry = (int)qrby, ilx = (int)qltx, irx = (int)qrbx;
        bool vly = (ily >= 1) && (ily <= 64), vry = (iry >= 1) && (iry <= 64);
        bool vlx = (ilx >= 1) && (ilx <= 64), vrx = (irx >= 1) && (irx <= 64);
        int bly = (ily - 1) << 6, bry = (iry - 1) << 6;
        unsigned short i0 = (vly && vlx) ? (unsigned short)(bly + ilx - 1) : 0;
        float w0 = (vly && vlx) ? dly * dlx : 0.f;
        unsigned short i1 = (vry && vrx) ? (unsigned short)(bry + irx - 1) : 0;
        float w1 = (vry && vrx) ? dry * drx : 0.f;
        unsigned short i2 = (vly && vrx) ? (unsigned short)(bly + irx - 1) : 0;
        float w2 = (vly && vrx) ? dly * drx : 0.f;
        unsigned short i3 = (vry && vlx) ? (unsigned short)(bry + ilx - 1) : 0;
        float w3 = (vry && vlx) ? dry * dlx : 0.f;
        tabi[e] = make_ushort4(i0, i1, i2, i3);
        tabw[e] = make_float4(w0, w1, w2, w3);
    }
    __syncthreads();

    // ---- prologue: chunk 0 into buffer 0 ----
    load_W(smb + OFF_W, 0, tid);
    asm volatile("cp.async.commit_group;" ::: "memory");
    produce_S(sm + OFF_S, xb, tabi, tabw, 0, tid);

    float d[4][4][4];
#pragma unroll
    for (int mt = 0; mt < 4; mt++)
#pragma unroll
        for (int nt = 0; nt < 4; nt++)
#pragma unroll
            for (int q = 0; q < 4; q++) d[mt][nt][q] = 0.f;

    // ---- main loop: 72 K-chunks of 32 ----
    for (int ch = 0; ch < 72; ch++) {
        asm volatile("cp.async.wait_group 0;" ::: "memory");
        __syncthreads();

        uint32_t wbase = smb + OFF_W + (ch & 1) * WBUF;
        uint32_t sbase = smb + OFF_S + (ch & 1) * SBUF;

        if (ch + 1 < 72) {
            int nb2 = (ch + 1) & 1;
            load_W(smb + OFF_W + nb2 * WBUF, ch + 1, tid);
            asm volatile("cp.async.commit_group;" ::: "memory");
            produce_S(sm + OFF_S + nb2 * SBUF, xb, tabi, tabw, ch + 1, tid);
        }

#pragma unroll
        for (int kk = 0; kk < 2; kk++) {
            uint32_t bh[4][2], bl[4][2];
#pragma unroll
            for (int nt = 0; nt < 4; nt++) {
                uint32_t baddr = sbase + (wn * 32 + nt * 8 + (lane & 7)) * RSTRIDE
                               + (kk * 16 + ((lane >> 3) & 1) * 8) * 2;
                ldsm2(bh[nt], baddr);
                ldsm2(bl[nt], baddr + 10240);
            }
#pragma unroll
            for (int mt = 0; mt < 4; mt++) {
                uint32_t aaddr = wbase + (wm * 64 + mt * 16 + (lane & 15)) * RSTRIDE
                               + (kk * 16 + (lane >> 4) * 8) * 2;
                uint32_t ah[4], al[4];
                ldsm4(ah, aaddr);
                ldsm4(al, aaddr + 20480);
#pragma unroll
                for (int nt = 0; nt < 4; nt++) {
                    mma16816(d[mt][nt], ah, bh[nt]);   // hi*hi
                    mma16816(d[mt][nt], ah, bl[nt]);   // hi*lo
                    mma16816(d[mt][nt], al, bh[nt]);   // lo*hi
                }
            }
        }
    }

    // ---- epilogue: store accumulators ----
    // lane l: rows l>>2 (+8), cols 2*(l&3)+{0,1} within each 16x8 tile
    int g4 = lane >> 2;
    int t4 = lane & 3;
#pragma unroll
    for (int mt = 0; mt < 4; mt++) {
#pragma unroll
        for (int nt = 0; nt < 4; nt++) {
            int pixb = wn * 32 + nt * 8 + t4 * 2;
            int h = h0 + (pixb >> 6);
            int w = pixb & 63;
            int oc0 = wm * 64 + mt * 16 + g4;
            float* p0 = out + ((size_t)b << 20) + ((size_t)oc0 << 12) + (h << 6) + w;
            *(float2*)p0 = make_float2(d[mt][nt][0], d[mt][nt][1]);
            float* p1 = p0 + (8 << 12);   // oc0 + 8
            *(float2*)p1 = make_float2(d[mt][nt][2], d[mt][nt][3]);
        }
    }
}

// ---------------------------------------------------------------------------
extern "C" void kernel_launch(void* const* d_in, const int* in_sizes, int n_in,
                              void* d_out, int out_size) {
    const float* x  = (const float*)d_in[0];
    const float* pw = (const float*)d_in[1];
    const float* pb = (const float*)d_in[2];
    const float* cw = (const float*)d_in[3];
    float* out = (float*)d_out;

    cudaFuncSetAttribute(k_main, cudaFuncAttributeMaxDynamicSharedMemorySize, SMEM_SZ);

    k_prep<<<KTOT, 256>>>(cw);
    k_offset<<<NB * NH, 256>>>(x, pw, pb);
    k_main<<<128, 512, SMEM_SZ>>>(x, out);
}

// round 10
// speedup vs baseline: 1.7493x; 1.1204x over previous
#include <cuda_runtime.h>
#include <cuda_bf16.h>
#include <cuda_fp16.h>
#include <cstdint>

// x(4,256,64,64), p_w(18,256,3,3), p_b(18), conv_w(256,256,3,3) -> out(4,256,64,64)
#define NB   4
#define NH   64
#define NW   64
#define KTOT 2304   // 256*9

__device__ float g_off[NB * 18 * NH * NW];
__device__ __align__(16) __half g_whi[256 * KTOT];  // [oc][k] fp16 hi limb
__device__ __align__(16) __half g_wlo[256 * KTOT];  // [oc][k] fp16 lo limb

// ---------------------------------------------------------------------------
// Kernel 0: split conv_w into fp16 hi/lo limbs, layout [oc][k]
// ---------------------------------------------------------------------------
__global__ void k_prep(const float* __restrict__ w) {
    int e = blockIdx.x * 256 + threadIdx.x;    // 589824 exact
    float v = w[e];
    __half h = __float2half_rn(v);
    __half l = __float2half_rn(v - __half2float(h));
    g_whi[e] = h;
    g_wlo[e] = l;
}

// ---------------------------------------------------------------------------
// Kernel 1: offset conv (unchanged from passing version)
// ---------------------------------------------------------------------------
__global__ void __launch_bounds__(256) k_offset(const float* __restrict__ x,
                                                const float* __restrict__ pw,
                                                const float* __restrict__ pb) {
    __shared__ __align__(16) float patch[4][3][68];
    __shared__ __align__(16) float ws[4][9][20];
    __shared__ float red[4][64][18];

    int b = blockIdx.x >> 6;
    int h = blockIdx.x & 63;
    int tid = threadIdx.x;
    int g   = tid >> 6;
    int pix = tid & 63;

    float acc[20];
#pragma unroll
    for (int i = 0; i < 20; i++) acc[i] = 0.f;

    const float* xb = x + ((size_t)b << 20);

    for (int cc = 0; cc < 64; cc++) {
        for (int l = tid; l < 4 * 3 * 66; l += 256) {
            int gg  = l / 198;
            int rem = l - gg * 198;
            int r   = rem / 66;
            int wc  = rem - r * 66;
            int y   = h + r - 1;
            int xw  = wc - 1;
            float v = 0.f;
            if (y >= 0 && y < NH && xw >= 0 && xw < NW)
                v = xb[((gg * 64 + cc) << 12) + (y << 6) + xw];
            patch[gg][r][wc] = v;
        }
        for (int l = tid; l < 720; l += 256) {
            int gg  = l / 180;
            int rem = l - gg * 180;
            int n   = rem / 20;
            int oc  = rem - n * 20;
            float v = 0.f;
            if (oc < 18) v = pw[oc * KTOT + (gg * 64 + cc) * 9 + n];
            ws[gg][n][oc] = v;
        }
        __syncthreads();

#pragma unroll
        for (int ky = 0; ky < 3; ky++) {
#pragma unroll
            for (int kx = 0; kx < 3; kx++) {
                float s = patch[g][ky][pix + kx];
                int n = ky * 3 + kx;
#pragma unroll
                for (int q = 0; q < 5; q++) {
                    float4 w4 = *(const float4*)&ws[g][n][q * 4];
                    acc[q * 4 + 0] += w4.x * s;
                    acc[q * 4 + 1] += w4.y * s;
                    acc[q * 4 + 2] += w4.z * s;
                    acc[q * 4 + 3] += w4.w * s;
                }
            }
        }
        __syncthreads();
    }

#pragma unroll
    for (int i = 0; i < 18; i++) red[g][pix][i] = acc[i];
    __syncthreads();

    for (int e = tid; e < 64 * 18; e += 256) {
        int p2 = e / 18;
        int oc = e - p2 * 18;
        float v = red[0][p2][oc] + red[1][p2][oc] + red[2][p2][oc] + red[3][p2][oc] + pb[oc];
        g_off[((b * 18 + oc) << 12) + (h << 6) + p2] = v;
    }
}

// ---------------------------------------------------------------------------
// Kernel 2: warp-level fp16 mma.sync 2-pass implicit GEMM + fused sampling
// CTA: 256 oc x 128 px, 512 thr = 16 warps (4M x 4N), warp tile 64x32.
// K=2304 in 72 chunks of 32. smem rows padded to 80B (conflict-free ldmatrix).
// out = (W_hi + W_lo) * S_fp16 : dropped term W*S_lo ~ 2^-11 -> out err ~1.5e-4
// ---------------------------------------------------------------------------
#define OFF_TABI 0          // ushort4[1152]   9216 B
#define OFF_TABW 9216       // float4 [1152]  18432 B
#define OFF_W    27648      // 2 buf x (hi 20480 + lo 20480) = 81920
#define WBUF     40960
#define OFF_S    109568     // 2 buf x 10240 = 20480
#define SBUF     10240
#define SMEM_SZ  130048
#define RSTRIDE  80         // bytes per k-row (32 fp16 = 64B + 16B pad)

__device__ __forceinline__ void cp16(uint32_t smem_dst, const void* gsrc) {
    asm volatile("cp.async.cg.shared.global [%0], [%1], 16;" ::"r"(smem_dst), "l"(gsrc));
}
__device__ __forceinline__ void ldsm4(uint32_t a[4], uint32_t addr) {
    asm volatile("ldmatrix.sync.aligned.m8n8.x4.shared.b16 {%0,%1,%2,%3}, [%4];"
                 : "=r"(a[0]), "=r"(a[1]), "=r"(a[2]), "=r"(a[3]) : "r"(addr));
}
__device__ __forceinline__ void ldsm2(uint32_t a[2], uint32_t addr) {
    asm volatile("ldmatrix.sync.aligned.m8n8.x2.shared.b16 {%0,%1}, [%2];"
                 : "=r"(a[0]), "=r"(a[1]) : "r"(addr));
}
__device__ __forceinline__ void mma16816(float d[4], const uint32_t a[4], const uint32_t b[2]) {
    asm volatile(
        "mma.sync.aligned.m16n8k16.row.col.f32.f16.f16.f32 "
        "{%0,%1,%2,%3}, {%4,%5,%6,%7}, {%8,%9}, {%0,%1,%2,%3};"
        : "+f"(d[0]), "+f"(d[1]), "+f"(d[2]), "+f"(d[3])
        : "r"(a[0]), "r"(a[1]), "r"(a[2]), "r"(a[3]), "r"(b[0]), "r"(b[1]));
}

// load W chunk ch (32 k) into buffer: hi[256][80B] + lo[256][80B]
__device__ __forceinline__ void load_W(uint32_t wbase, int ch, int tid) {
#pragma unroll
    for (int j = 0; j < 4; j++) {
        int idx = tid + (j << 9);       // 0..2047
        int t   = idx >> 10;            // 0=hi, 1=lo
        int r10 = idx & 1023;
        int oc  = r10 >> 2;
        int c16 = r10 & 3;
        const __half* gw = t ? g_wlo : g_whi;
        cp16(wbase + t * 20480 + oc * RSTRIDE + c16 * 16,
             gw + (size_t)oc * KTOT + ch * 32 + c16 * 8);
    }
}

// produce S chunk ch: fp16 [128 pix][80B rows]
__device__ __forceinline__ void produce_S(char* sbase, const float* __restrict__ xb,
                                          const ushort4* tabi, const float4* tabw,
                                          int ch, int tid) {
#pragma unroll
    for (int j = 0; j < 4; j++) {
        int idx = tid + (j << 9);       // 0..2047 (fp16 word-pairs)
        int kk2 = idx >> 7;             // 0..15
        int pix = idx & 127;
        uint32_t hbits = 0;
#pragma unroll
        for (int u = 0; u < 2; u++) {
            int k  = ch * 32 + kk2 * 2 + u;
            int ci = k / 9;
            int n  = k - ci * 9;
            ushort4 id = tabi[pix * 9 + n];
            float4  wg = tabw[pix * 9 + n];
            const float* xp = xb + (ci << 12);
            float s = wg.x * xp[id.x] + wg.y * xp[id.y] + wg.z * xp[id.z] + wg.w * xp[id.w];
            hbits |= (uint32_t)__half_as_ushort(__float2half_rn(s)) << (u * 16);
        }
        *(uint32_t*)(sbase + pix * RSTRIDE + kk2 * 4) = hbits;
    }
}

__global__ void __launch_bounds__(512, 1) k_main(const float* __restrict__ x,
                                                 float* __restrict__ out) {
    extern __shared__ __align__(16) char sm[];
    uint32_t smb = (uint32_t)__cvta_generic_to_shared(sm);
    int tid  = threadIdx.x;
    int wid  = tid >> 5;
    int lane = tid & 31;
    int wm   = wid >> 2;              // 0..3 -> oc base wm*64
    int wn   = wid & 3;               // 0..3 -> pix base wn*32
    int b    = blockIdx.x >> 5;
    int h0   = (blockIdx.x & 31) * 2;
    const float* xb = x + ((size_t)b << 20);

    ushort4* tabi = (ushort4*)(sm + OFF_TABI);
    float4*  tabw = (float4*)(sm + OFF_TABW);

    // ---- bilinear tables: 128 pixels x 9 taps ----
    for (int e = tid; e < 1152; e += 512) {
        int pix = e / 9;
        int n   = e - pix * 9;
        int h   = h0 + (pix >> 6);
        int w   = pix & 63;
        int gbase = ((b * 18 + n) << 12) + (h << 6) + w;
        float offy = g_off[gbase];
        float offx = g_off[gbase + (9 << 12)];
        int ky = n / 3;
        int kx = n - ky * 3;
        float py = (float)(h + ky) + offy;
        float px = (float)(w + kx) + offx;
        float fy = floorf(py), fx = floorf(px);
        float qlty = fminf(fmaxf(fy, 0.f), 65.f);
        float qrby = fminf(fmaxf(fy + 1.f, 0.f), 65.f);
        float qltx = fminf(fmaxf(fx, 0.f), 65.f);
        float qrbx = fminf(fmaxf(fx + 1.f, 0.f), 65.f);
        float pyc = fminf(fmaxf(py, 0.f), 65.f);
        float pxc = fminf(fmaxf(px, 0.f), 65.f);
        float dly = 1.f + qlty - pyc, dry = 1.f - qrby + pyc;
        float dlx = 1.f + qltx - pxc, drx = 1.f - qrbx + pxc;
        int ily = (int)qlty, iry = (int)qrby, ilx = (int)qltx, irx = (int)qrbx;
        bool vly = (ily >= 1) && (ily <= 64), vry = (iry >= 1) && (iry <= 64);
        bool vlx = (ilx >= 1) && (ilx <= 64), vrx = (irx >= 1) && (irx <= 64);
        int bly = (ily - 1) << 6, bry = (iry - 1) << 6;
        unsigned short i0 = (vly && vlx) ? (unsigned short)(bly + ilx - 1) : 0;
        float w0 = (vly && vlx) ? dly * dlx : 0.f;
        unsigned short i1 = (vry && vrx) ? (unsigned short)(bry + irx - 1) : 0;
        float w1 = (vry && vrx) ? dry * drx : 0.f;
        unsigned short i2 = (vly && vrx) ? (unsigned short)(bly + irx - 1) : 0;
        float w2 = (vly && vrx) ? dly * drx : 0.f;
        unsigned short i3 = (vry && vlx) ? (unsigned short)(bry + ilx - 1) : 0;
        float w3 = (vry && vlx) ? dry * dlx : 0.f;
        tabi[e] = make_ushort4(i0, i1, i2, i3);
        tabw[e] = make_float4(w0, w1, w2, w3);
    }
    __syncthreads();

    // ---- prologue: chunk 0 into buffer 0 ----
    load_W(smb + OFF_W, 0, tid);
    asm volatile("cp.async.commit_group;" ::: "memory");
    produce_S(sm + OFF_S, xb, tabi, tabw, 0, tid);

    float d[4][4][4];
#pragma unroll
    for (int mt = 0; mt < 4; mt++)
#pragma unroll
        for (int nt = 0; nt < 4; nt++)
#pragma unroll
            for (int q = 0; q < 4; q++) d[mt][nt][q] = 0.f;

    // ---- main loop: 72 K-chunks of 32 ----
    for (int ch = 0; ch < 72; ch++) {
        asm volatile("cp.async.wait_group 0;" ::: "memory");
        __syncthreads();

        uint32_t wbase = smb + OFF_W + (ch & 1) * WBUF;
        uint32_t sbase = smb + OFF_S + (ch & 1) * SBUF;

        if (ch + 1 < 72) {
            int nb2 = (ch + 1) & 1;
            load_W(smb + OFF_W + nb2 * WBUF, ch + 1, tid);
            asm volatile("cp.async.commit_group;" ::: "memory");
            produce_S(sm + OFF_S + nb2 * SBUF, xb, tabi, tabw, ch + 1, tid);
        }

#pragma unroll
        for (int kk = 0; kk < 2; kk++) {
            uint32_t bh[4][2];
#pragma unroll
            for (int nt = 0; nt < 4; nt++) {
                uint32_t baddr = sbase + (wn * 32 + nt * 8 + (lane & 7)) * RSTRIDE
                               + (kk * 16 + ((lane >> 3) & 1) * 8) * 2;
                ldsm2(bh[nt], baddr);
            }
#pragma unroll
            for (int mt = 0; mt < 4; mt++) {
                uint32_t aaddr = wbase + (wm * 64 + mt * 16 + (lane & 15)) * RSTRIDE
                               + (kk * 16 + (lane >> 4) * 8) * 2;
                uint32_t ah[4], al[4];
                ldsm4(ah, aaddr);
                ldsm4(al, aaddr + 20480);
#pragma unroll
                for (int nt = 0; nt < 4; nt++) {
                    mma16816(d[mt][nt], ah, bh[nt]);   // W_hi * S
                    mma16816(d[mt][nt], al, bh[nt]);   // W_lo * S
                }
            }
        }
    }

    // ---- epilogue: store accumulators ----
    int g4 = lane >> 2;
    int t4 = lane & 3;
#pragma unroll
    for (int mt = 0; mt < 4; mt++) {
#pragma unroll
        for (int nt = 0; nt < 4; nt++) {
            int pixb = wn * 32 + nt * 8 + t4 * 2;
            int h = h0 + (pixb >> 6);
            int w = pixb & 63;
            int oc0 = wm * 64 + mt * 16 + g4;
            float* p0 = out + ((size_t)b << 20) + ((size_t)oc0 << 12) + (h << 6) + w;
            *(float2*)p0 = make_float2(d[mt][nt][0], d[mt][nt][1]);
            float* p1 = p0 + (8 << 12);   // oc0 + 8
            *(float2*)p1 = make_float2(d[mt][nt][2], d[mt][nt][3]);
        }
    }
}

// ---------------------------------------------------------------------------
extern "C" void kernel_launch(void* const* d_in, const int* in_sizes, int n_in,
                              void* d_out, int out_size) {
    const float* x  = (const float*)d_in[0];
    const float* pw = (const float*)d_in[1];
    const float* pb = (const float*)d_in[2];
    const float* cw = (const float*)d_in[3];
    float* out = (float*)d_out;

    cudaFuncSetAttribute(k_main, cudaFuncAttributeMaxDynamicSharedMemorySize, SMEM_SZ);

    k_prep<<<KTOT, 256>>>(cw);
    k_offset<<<NB * NH, 256>>>(x, pw, pb);
    k_main<<<128, 512, SMEM_SZ>>>(x, out);
}

// round 11
// speedup vs baseline: 2.1369x; 1.2216x over previous
#include <cuda_runtime.h>
#include <cuda_bf16.h>
#include <cuda_fp16.h>
#include <cstdint>

// x(4,256,64,64), p_w(18,256,3,3), p_b(18), conv_w(256,256,3,3) -> out(4,256,64,64)
#define NB   4
#define NH   64
#define NW   64
#define KTOT 2304   // 256*9

__device__ float g_off[NB * 18 * NH * NW];
__device__ __align__(16) __half g_whi[256 * KTOT];  // [oc][k] fp16(W)

// ---------------------------------------------------------------------------
// Kernel 0: round conv_w to fp16, layout [oc][k]
// ---------------------------------------------------------------------------
__global__ void k_prep(const float* __restrict__ w) {
    int e = blockIdx.x * 256 + threadIdx.x;    // 589824 exact
    g_whi[e] = __float2half_rn(w[e]);
}

// ---------------------------------------------------------------------------
// Kernel 1: offset conv (unchanged from passing version)
// ---------------------------------------------------------------------------
__global__ void __launch_bounds__(256) k_offset(const float* __restrict__ x,
                                                const float* __restrict__ pw,
                                                const float* __restrict__ pb) {
    __shared__ __align__(16) float patch[4][3][68];
    __shared__ __align__(16) float ws[4][9][20];
    __shared__ float red[4][64][18];

    int b = blockIdx.x >> 6;
    int h = blockIdx.x & 63;
    int tid = threadIdx.x;
    int g   = tid >> 6;
    int pix = tid & 63;

    float acc[20];
#pragma unroll
    for (int i = 0; i < 20; i++) acc[i] = 0.f;

    const float* xb = x + ((size_t)b << 20);

    for (int cc = 0; cc < 64; cc++) {
        for (int l = tid; l < 4 * 3 * 66; l += 256) {
            int gg  = l / 198;
            int rem = l - gg * 198;
            int r   = rem / 66;
            int wc  = rem - r * 66;
            int y   = h + r - 1;
            int xw  = wc - 1;
            float v = 0.f;
            if (y >= 0 && y < NH && xw >= 0 && xw < NW)
                v = xb[((gg * 64 + cc) << 12) + (y << 6) + xw];
            patch[gg][r][wc] = v;
        }
        for (int l = tid; l < 720; l += 256) {
            int gg  = l / 180;
            int rem = l - gg * 180;
            int n   = rem / 20;
            int oc  = rem - n * 20;
            float v = 0.f;
            if (oc < 18) v = pw[oc * KTOT + (gg * 64 + cc) * 9 + n];
            ws[gg][n][oc] = v;
        }
        __syncthreads();

#pragma unroll
        for (int ky = 0; ky < 3; ky++) {
#pragma unroll
            for (int kx = 0; kx < 3; kx++) {
                float s = patch[g][ky][pix + kx];
                int n = ky * 3 + kx;
#pragma unroll
                for (int q = 0; q < 5; q++) {
                    float4 w4 = *(const float4*)&ws[g][n][q * 4];
                    acc[q * 4 + 0] += w4.x * s;
                    acc[q * 4 + 1] += w4.y * s;
                    acc[q * 4 + 2] += w4.z * s;
                    acc[q * 4 + 3] += w4.w * s;
                }
            }
        }
        __syncthreads();
    }

#pragma unroll
    for (int i = 0; i < 18; i++) red[g][pix][i] = acc[i];
    __syncthreads();

    for (int e = tid; e < 64 * 18; e += 256) {
        int p2 = e / 18;
        int oc = e - p2 * 18;
        float v = red[0][p2][oc] + red[1][p2][oc] + red[2][p2][oc] + red[3][p2][oc] + pb[oc];
        g_off[((b * 18 + oc) << 12) + (h << 6) + p2] = v;
    }
}

// ---------------------------------------------------------------------------
// Kernel 2: warp-level fp16 mma.sync single-pass implicit GEMM + fused sampling
// CTA: 256 oc x 128 px, 512 thr = 16 warps (4M x 4N), warp tile 64x32.
// K=2304 in 36 chunks of 64. smem rows 144B (64 fp16 + 16B pad; conflict-free ldsm).
// ---------------------------------------------------------------------------
#define OFF_TABI 0          // ushort4[1152]   9216 B
#define OFF_TABW 9216       // float4 [1152]  18432 B
#define OFF_W    27648      // 2 buf x 36864 (256 rows x 144B)
#define WBUF     36864
#define OFF_S    101376     // 2 buf x 18432 (128 rows x 144B)
#define SBUF     18432
#define SMEM_SZ  138240
#define RSTRIDE  144        // bytes per k-row

__device__ __forceinline__ void cp16(uint32_t smem_dst, const void* gsrc) {
    asm volatile("cp.async.cg.shared.global [%0], [%1], 16;" ::"r"(smem_dst), "l"(gsrc));
}
__device__ __forceinline__ void ldsm4(uint32_t a[4], uint32_t addr) {
    asm volatile("ldmatrix.sync.aligned.m8n8.x4.shared.b16 {%0,%1,%2,%3}, [%4];"
                 : "=r"(a[0]), "=r"(a[1]), "=r"(a[2]), "=r"(a[3]) : "r"(addr));
}
__device__ __forceinline__ void ldsm2(uint32_t a[2], uint32_t addr) {
    asm volatile("ldmatrix.sync.aligned.m8n8.x2.shared.b16 {%0,%1}, [%2];"
                 : "=r"(a[0]), "=r"(a[1]) : "r"(addr));
}
__device__ __forceinline__ void mma16816(float d[4], const uint32_t a[4], const uint32_t b[2]) {
    asm volatile(
        "mma.sync.aligned.m16n8k16.row.col.f32.f16.f16.f32 "
        "{%0,%1,%2,%3}, {%4,%5,%6,%7}, {%8,%9}, {%0,%1,%2,%3};"
        : "+f"(d[0]), "+f"(d[1]), "+f"(d[2]), "+f"(d[3])
        : "r"(a[0]), "r"(a[1]), "r"(a[2]), "r"(a[3]), "r"(b[0]), "r"(b[1]));
}

// load W chunk ch (64 k) into buffer: [256 oc][144B rows]
__device__ __forceinline__ void load_W(uint32_t wbase, int ch, int tid) {
#pragma unroll
    for (int j = 0; j < 4; j++) {
        int idx = tid + (j << 9);       // 0..2047 (16B chunks)
        int oc  = idx >> 3;
        int c16 = idx & 7;
        cp16(wbase + oc * RSTRIDE + c16 * 16,
             g_whi + (size_t)oc * KTOT + ch * 64 + c16 * 8);
    }
}

// produce S chunk ch: fp16 [128 pix][144B rows], 64 k per row
__device__ __forceinline__ void produce_S(char* sbase, const float* __restrict__ xb,
                                          const ushort4* tabi, const float4* tabw,
                                          int ch, int tid) {
#pragma unroll
    for (int j = 0; j < 8; j++) {
        int idx = tid + (j << 9);       // 0..4095 (fp16 word-pairs)
        int kk2 = idx >> 7;             // 0..31
        int pix = idx & 127;
        uint32_t hbits = 0;
#pragma unroll
        for (int u = 0; u < 2; u++) {
            int k  = ch * 64 + kk2 * 2 + u;
            int ci = k / 9;
            int n  = k - ci * 9;
            ushort4 id = tabi[pix * 9 + n];
            float4  wg = tabw[pix * 9 + n];
            const float* xp = xb + (ci << 12);
            float s = wg.x * xp[id.x] + wg.y * xp[id.y] + wg.z * xp[id.z] + wg.w * xp[id.w];
            hbits |= (uint32_t)__half_as_ushort(__float2half_rn(s)) << (u * 16);
        }
        *(uint32_t*)(sbase + pix * RSTRIDE + kk2 * 4) = hbits;
    }
}

__global__ void __launch_bounds__(512, 1) k_main(const float* __restrict__ x,
                                                 float* __restrict__ out) {
    extern __shared__ __align__(16) char sm[];
    uint32_t smb = (uint32_t)__cvta_generic_to_shared(sm);
    int tid  = threadIdx.x;
    int wid  = tid >> 5;
    int lane = tid & 31;
    int wm   = wid >> 2;              // 0..3 -> oc base wm*64
    int wn   = wid & 3;               // 0..3 -> pix base wn*32
    int b    = blockIdx.x >> 5;
    int h0   = (blockIdx.x & 31) * 2;
    const float* xb = x + ((size_t)b << 20);

    ushort4* tabi = (ushort4*)(sm + OFF_TABI);
    float4*  tabw = (float4*)(sm + OFF_TABW);

    // ---- bilinear tables: 128 pixels x 9 taps ----
    for (int e = tid; e < 1152; e += 512) {
        int pix = e / 9;
        int n   = e - pix * 9;
        int h   = h0 + (pix >> 6);
        int w   = pix & 63;
        int gbase = ((b * 18 + n) << 12) + (h << 6) + w;
        float offy = g_off[gbase];
        float offx = g_off[gbase + (9 << 12)];
        int ky = n / 3;
        int kx = n - ky * 3;
        float py = (float)(h + ky) + offy;
        float px = (float)(w + kx) + offx;
        float fy = floorf(py), fx = floorf(px);
        float qlty = fminf(fmaxf(fy, 0.f), 65.f);
        float qrby = fminf(fmaxf(fy + 1.f, 0.f), 65.f);
        float qltx = fminf(fmaxf(fx, 0.f), 65.f);
        float qrbx = fminf(fmaxf(fx + 1.f, 0.f), 65.f);
        float pyc = fminf(fmaxf(py, 0.f), 65.f);
        float pxc = fminf(fmaxf(px, 0.f), 65.f);
        float dly = 1.f + qlty - pyc, dry = 1.f - qrby + pyc;
        float dlx = 1.f + qltx - pxc, drx = 1.f - qrbx + pxc;
        int ily = (int)qlty, iry = (int)qrby, ilx = (int)qltx, irx = (int)qrbx;
        bool vly = (ily >= 1) && (ily <= 64), vry = (iry >= 1) && (iry <= 64);
        bool vlx = (ilx >= 1) && (ilx <= 64), vrx = (irx >= 1) && (irx <= 64);
        int bly = (ily - 1) << 6, bry = (iry - 1) << 6;
        unsigned short i0 = (vly && vlx) ? (unsigned short)(bly + ilx - 1) : 0;
        float w0 = (vly && vlx) ? dly * dlx : 0.f;
        unsigned short i1 = (vry && vrx) ? (unsigned short)(bry + irx - 1) : 0;
        float w1 = (vry && vrx) ? dry * drx : 0.f;
        unsigned short i2 = (vly && vrx) ? (unsigned short)(bly + irx - 1) : 0;
        float w2 = (vly && vrx) ? dly * drx : 0.f;
        unsigned short i3 = (vry && vlx) ? (unsigned short)(bry + ilx - 1) : 0;
        float w3 = (vry && vlx) ? dry * dlx : 0.f;
        tabi[e] = make_ushort4(i0, i1, i2, i3);
        tabw[e] = make_float4(w0, w1, w2, w3);
    }
    __syncthreads();

    // ---- prologue: chunk 0 into buffer 0 ----
    load_W(smb + OFF_W, 0, tid);
    asm volatile("cp.async.commit_group;" ::: "memory");
    produce_S(sm + OFF_S, xb, tabi, tabw, 0, tid);

    float d[4][4][4];
#pragma unroll
    for (int mt = 0; mt < 4; mt++)
#pragma unroll
        for (int nt = 0; nt < 4; nt++)
#pragma unroll
            for (int q = 0; q < 4; q++) d[mt][nt][q] = 0.f;

    // ---- main loop: 36 K-chunks of 64 ----
    for (int ch = 0; ch < 36; ch++) {
        asm volatile("cp.async.wait_group 0;" ::: "memory");
        __syncthreads();

        uint32_t wbase = smb + OFF_W + (ch & 1) * WBUF;
        uint32_t sbase = smb + OFF_S + (ch & 1) * SBUF;

        if (ch + 1 < 36) {
            int nb2 = (ch + 1) & 1;
            load_W(smb + OFF_W + nb2 * WBUF, ch + 1, tid);
            asm volatile("cp.async.commit_group;" ::: "memory");
            produce_S(sm + OFF_S + nb2 * SBUF, xb, tabi, tabw, ch + 1, tid);
        }

#pragma unroll
        for (int kk = 0; kk < 4; kk++) {
            uint32_t bh[4][2];
#pragma unroll
            for (int nt = 0; nt < 4; nt++) {
                uint32_t baddr = sbase + (wn * 32 + nt * 8 + (lane & 7)) * RSTRIDE
                               + (kk * 16 + ((lane >> 3) & 1) * 8) * 2;
                ldsm2(bh[nt], baddr);
            }
#pragma unroll
            for (int mt = 0; mt < 4; mt++) {
                uint32_t aaddr = wbase + (wm * 64 + mt * 16 + (lane & 15)) * RSTRIDE
                               + (kk * 16 + (lane >> 4) * 8) * 2;
                uint32_t ah[4];
                ldsm4(ah, aaddr);
#pragma unroll
                for (int nt = 0; nt < 4; nt++)
                    mma16816(d[mt][nt], ah, bh[nt]);
            }
        }
    }

    // ---- epilogue: store accumulators ----
    int g4 = lane >> 2;
    int t4 = lane & 3;
#pragma unroll
    for (int mt = 0; mt < 4; mt++) {
#pragma unroll
        for (int nt = 0; nt < 4; nt++) {
            int pixb = wn * 32 + nt * 8 + t4 * 2;
            int h = h0 + (pixb >> 6);
            int w = pixb & 63;
            int oc0 = wm * 64 + mt * 16 + g4;
            float* p0 = out + ((size_t)b << 20) + ((size_t)oc0 << 12) + (h << 6) + w;
            *(float2*)p0 = make_float2(d[mt][nt][0], d[mt][nt][1]);
            float* p1 = p0 + (8 << 12);   // oc0 + 8
            *(float2*)p1 = make_float2(d[mt][nt][2], d[mt][nt][3]);
        }
    }
}

// ---------------------------------------------------------------------------
extern "C" void kernel_launch(void* const* d_in, const int* in_sizes, int n_in,
                              void* d_out, int out_size) {
    const float* x  = (const float*)d_in[0];
    const float* pw = (const float*)d_in[1];
    const float* pb = (const float*)d_in[2];
    const float* cw = (const float*)d_in[3];
    float* out = (float*)d_out;

    cudaFuncSetAttribute(k_main, cudaFuncAttributeMaxDynamicSharedMemorySize, SMEM_SZ);

    k_prep<<<KTOT, 256>>>(cw);
    k_offset<<<NB * NH, 256>>>(x, pw, pb);
    k_main<<<128, 512, SMEM_SZ>>>(x, out);
}

// round 13
// speedup vs baseline: 2.1676x; 1.0144x over previous
#include <cuda_runtime.h>
#include <cuda_bf16.h>
#include <cuda_fp16.h>
#include <cstdint>

// x(4,256,64,64), p_w(18,256,3,3), p_b(18), conv_w(256,256,3,3) -> out(4,256,64,64)
#define NB   4
#define NH   64
#define NW   64
#define KTOT 2304   // 256*9

__device__ float g_off[NB * 18 * NH * NW];
__device__ __align__(16) __half g_whi[256 * KTOT];   // [oc][k] fp16(W)
// padded fp16 image, 2 parity copies of paired columns:
// [b][ch][copy(2)][row(66)][word(34)] u32 ; copyE word j = cols (2j,2j+1),
// copyO word j = cols (2j+1,2j+2). Rows/cols 0 & 65 are the zero pad ring.
#define CH_WORDS 4488   // 2*66*34
__device__ __align__(16) uint32_t g_xh[NB * 256 * CH_WORDS];

// ---------------------------------------------------------------------------
// Kernel 0a: round conv_w to fp16, layout [oc][k]
// ---------------------------------------------------------------------------
__global__ void k_prep(const float* __restrict__ w) {
    int e = blockIdx.x * 256 + threadIdx.x;    // 589824 exact
    g_whi[e] = __float2half_rn(w[e]);
}

// ---------------------------------------------------------------------------
// Kernel 0b: build padded fp16 paired-column copies of x
// ---------------------------------------------------------------------------
__global__ void k_prep2(const float* __restrict__ x) {
    int e = blockIdx.x * 256 + threadIdx.x;    // NB*256*CH_WORDS = 4595712 exact
    int word = e % CH_WORDS;
    int bc   = e / CH_WORDS;                   // b*256 + ch
    int copy = word / 2244;
    int rw   = word - copy * 2244;
    int row  = rw / 34;
    int j    = rw - row * 34;
    int p0   = 2 * j + copy;                   // first padded col of the pair
    const float* xc = x + (size_t)bc * 4096;
    float v0 = 0.f, v1 = 0.f;
    if (row >= 1 && row <= 64) {
        int c0 = p0, c1 = p0 + 1;
        if (c0 >= 1 && c0 <= 64) v0 = xc[(row - 1) * 64 + (c0 - 1)];
        if (c1 >= 1 && c1 <= 64) v1 = xc[(row - 1) * 64 + (c1 - 1)];
    }
    uint32_t h0 = __half_as_ushort(__float2half_rn(v0));
    uint32_t h1 = __half_as_ushort(__float2half_rn(v1));
    g_xh[e] = h0 | (h1 << 16);
}

// ---------------------------------------------------------------------------
// Kernel 1: offset conv (unchanged from passing version)
// ---------------------------------------------------------------------------
__global__ void __launch_bounds__(256) k_offset(const float* __restrict__ x,
                                                const float* __restrict__ pw,
                                                const float* __restrict__ pb) {
    __shared__ __align__(16) float patch[4][3][68];
    __shared__ __align__(16) float ws[4][9][20];
    __shared__ float red[4][64][18];

    int b = blockIdx.x >> 6;
    int h = blockIdx.x & 63;
    int tid = threadIdx.x;
    int g   = tid >> 6;
    int pix = tid & 63;

    float acc[20];
#pragma unroll
    for (int i = 0; i < 20; i++) acc[i] = 0.f;

    const float* xb = x + ((size_t)b << 20);

    for (int cc = 0; cc < 64; cc++) {
        for (int l = tid; l < 4 * 3 * 66; l += 256) {
            int gg  = l / 198;
            int rem = l - gg * 198;
            int r   = rem / 66;
            int wc  = rem - r * 66;
            int y   = h + r - 1;
            int xw  = wc - 1;
            float v = 0.f;
            if (y >= 0 && y < NH && xw >= 0 && xw < NW)
                v = xb[((gg * 64 + cc) << 12) + (y << 6) + xw];
            patch[gg][r][wc] = v;
        }
        for (int l = tid; l < 720; l += 256) {
            int gg  = l / 180;
            int rem = l - gg * 180;
            int n   = rem / 20;
            int oc  = rem - n * 20;
            float v = 0.f;
            if (oc < 18) v = pw[oc * KTOT + (gg * 64 + cc) * 9 + n];
            ws[gg][n][oc] = v;
        }
        __syncthreads();

#pragma unroll
        for (int ky = 0; ky < 3; ky++) {
#pragma unroll
            for (int kx = 0; kx < 3; kx++) {
                float s = patch[g][ky][pix + kx];
                int n = ky * 3 + kx;
#pragma unroll
                for (int q = 0; q < 5; q++) {
                    float4 w4 = *(const float4*)&ws[g][n][q * 4];
                    acc[q * 4 + 0] += w4.x * s;
                    acc[q * 4 + 1] += w4.y * s;
                    acc[q * 4 + 2] += w4.z * s;
                    acc[q * 4 + 3] += w4.w * s;
                }
            }
        }
        __syncthreads();
    }

#pragma unroll
    for (int i = 0; i < 18; i++) red[g][pix][i] = acc[i];
    __syncthreads();

    for (int e = tid; e < 64 * 18; e += 256) {
        int p2 = e / 18;
        int oc = e - p2 * 18;
        float v = red[0][p2][oc] + red[1][p2][oc] + red[2][p2][oc] + red[3][p2][oc] + pb[oc];
        g_off[((b * 18 + oc) << 12) + (h << 6) + p2] = v;
    }
}

// ---------------------------------------------------------------------------
// Kernel 2: warp-level fp16 mma.sync implicit GEMM + paired-load sampling
// CTA: 256 oc x 128 px, 512 thr = 16 warps (4M x 4N), warp tile 64x32.
// K=2304 in 36 chunks of 64. smem rows 144B (64 fp16 + 16B pad).
// ---------------------------------------------------------------------------
#define OFF_TABI 0          // uint[1152]      4608 B (utop | ubot<<16)
#define OFF_TABW 4608       // float4[1152]   18432 B (w_lo_t, w_hi_t, w_lo_b, w_hi_b)
#define OFF_W    23040      // 2 buf x 36864 (256 rows x 144B)
#define WBUF     36864
#define OFF_S    96768      // 2 buf x 18432 (128 rows x 144B)
#define SBUF     18432
#define SMEM_SZ  133632
#define RSTRIDE  144        // bytes per k-row

__device__ __forceinline__ void cp16(uint32_t smem_dst, const void* gsrc) {
    asm volatile("cp.async.cg.shared.global [%0], [%1], 16;" ::"r"(smem_dst), "l"(gsrc));
}
__device__ __forceinline__ void ldsm4(uint32_t a[4], uint32_t addr) {
    asm volatile("ldmatrix.sync.aligned.m8n8.x4.shared.b16 {%0,%1,%2,%3}, [%4];"
                 : "=r"(a[0]), "=r"(a[1]), "=r"(a[2]), "=r"(a[3]) : "r"(addr));
}
__device__ __forceinline__ void ldsm2(uint32_t a[2], uint32_t addr) {
    asm volatile("ldmatrix.sync.aligned.m8n8.x2.shared.b16 {%0,%1}, [%2];"
                 : "=r"(a[0]), "=r"(a[1]) : "r"(addr));
}
__device__ __forceinline__ void mma16816(float d[4], const uint32_t a[4], const uint32_t b[2]) {
    asm volatile(
        "mma.sync.aligned.m16n8k16.row.col.f32.f16.f16.f32 "
        "{%0,%1,%2,%3}, {%4,%5,%6,%7}, {%8,%9}, {%0,%1,%2,%3};"
        : "+f"(d[0]), "+f"(d[1]), "+f"(d[2]), "+f"(d[3])
        : "r"(a[0]), "r"(a[1]), "r"(a[2]), "r"(a[3]), "r"(b[0]), "r"(b[1]));
}

// load W chunk ch (64 k): [256 oc][144B rows]
__device__ __forceinline__ void load_W(uint32_t wbase, int ch, int tid) {
#pragma unroll
    for (int j = 0; j < 4; j++) {
        int idx = tid + (j << 9);       // 0..2047 (16B chunks)
        int oc  = idx >> 3;
        int c16 = idx & 7;
        cp16(wbase + oc * RSTRIDE + c16 * 16,
             g_whi + (size_t)oc * KTOT + ch * 64 + c16 * 8);
    }
}

// produce S chunk ch: fp16 [128 pix][144B rows], 64 k per row
__device__ __forceinline__ void produce_S(char* sbase, const uint32_t* __restrict__ xhb,
                                          const uint32_t* tabi, const float4* tabw,
                                          int ch, int tid) {
#pragma unroll
    for (int j = 0; j < 8; j++) {
        int idx = tid + (j << 9);       // 0..4095 (fp16 word-pairs)
        int kk2 = idx >> 7;             // 0..31
        int pix = idx & 127;
        uint32_t hbits = 0;
#pragma unroll
        for (int u = 0; u < 2; u++) {
            int k  = ch * 64 + kk2 * 2 + u;
            int ci = k / 9;
            int n  = k - ci * 9;
            uint32_t id = tabi[pix * 9 + n];
            float4  wg  = tabw[pix * 9 + n];
            const uint32_t* xc = xhb + (size_t)ci * CH_WORDS;
            uint32_t top = xc[id & 0xffffu];
            uint32_t bot = xc[id >> 16];
            float2 ft = __half22float2(*(__half2*)&top);
            float2 fb = __half22float2(*(__half2*)&bot);
            float s = wg.x * ft.x + wg.y * ft.y + wg.z * fb.x + wg.w * fb.y;
            hbits |= (uint32_t)__half_as_ushort(__float2half_rn(s)) << (u * 16);
        }
        *(uint32_t*)(sbase + pix * RSTRIDE + kk2 * 4) = hbits;
    }
}

__global__ void __launch_bounds__(512, 1) k_main(float* __restrict__ out) {
    extern __shared__ __align__(16) char sm[];
    uint32_t smb = (uint32_t)__cvta_generic_to_shared(sm);
    int tid  = threadIdx.x;
    int wid  = tid >> 5;
    int lane = tid & 31;
    int wm   = wid >> 2;              // 0..3 -> oc base wm*64
    int wn   = wid & 3;               // 0..3 -> pix base wn*32
    int b    = blockIdx.x >> 5;
    int h0   = (blockIdx.x & 31) * 2;
    const uint32_t* xhb = g_xh + (size_t)b * 256 * CH_WORDS;

    uint32_t* tabi = (uint32_t*)(sm + OFF_TABI);
    float4*   tabw = (float4*)(sm + OFF_TABW);

    // ---- bilinear tables: 128 pixels x 9 taps, paired-load form ----
    for (int e = tid; e < 1152; e += 512) {
        int pix = e / 9;
        int n   = e - pix * 9;
        int h   = h0 + (pix >> 6);
        int w   = pix & 63;
        int gbase = ((b * 18 + n) << 12) + (h << 6) + w;
        float offy = g_off[gbase];
        float offx = g_off[gbase + (9 << 12)];
        int ky = n / 3;
        int kx = n - ky * 3;
        float py = (float)(h + ky) + offy;     // padded coords
        float px = (float)(w + kx) + offx;
        float fy = floorf(py), fx = floorf(px);
        float qlty = fminf(fmaxf(fy, 0.f), 65.f);
        float qrby = fminf(fmaxf(fy + 1.f, 0.f), 65.f);
        float qltx = fminf(fmaxf(fx, 0.f), 65.f);
        float qrbx = fminf(fmaxf(fx + 1.f, 0.f), 65.f);
        float pyc = fminf(fmaxf(py, 0.f), 65.f);
        float pxc = fminf(fmaxf(px, 0.f), 65.f);
        float dly = 1.f + qlty - pyc, dry = 1.f - qrby + pyc;
        float dlx = 1.f + qltx - pxc, drx = 1.f - qrbx + pxc;
        // corner weights (reference): lt=(qlty,qltx) rb=(qrby,qrbx) lb=(qlty,qrbx) rt=(qrby,qltx)
        float g_lt = dly * dlx, g_rb = dry * drx, g_lb = dly * drx, g_rt = dry * dlx;
        int ily = (int)qlty, iry = (int)qrby, ilx = (int)qltx, irx = (int)qrbx;
        // pair word contains cols (ilx, ilx+1); fold the x-degenerate case irx==ilx
        bool foldx = (irx == ilx);
        float w_lo_t = g_lt + (foldx ? g_lb : 0.f);
        float w_hi_t = foldx ? 0.f : g_lb;
        float w_lo_b = g_rt + (foldx ? g_rb : 0.f);
        float w_hi_b = foldx ? 0.f : g_rb;
        int cpy = ilx & 1;
        int wj  = (ilx - cpy) >> 1;
        uint32_t utop = (uint32_t)(cpy * 2244 + ily * 34 + wj);
        uint32_t ubot = (uint32_t)(cpy * 2244 + iry * 34 + wj);
        tabi[e] = utop | (ubot << 16);
        tabw[e] = make_float4(w_lo_t, w_hi_t, w_lo_b, w_hi_b);
    }
    __syncthreads();

    // ---- prologue: chunk 0 into buffer 0 ----
    load_W(smb + OFF_W, 0, tid);
    asm volatile("cp.async.commit_group;" ::: "memory");
    produce_S(sm + OFF_S, xhb, tabi, tabw, 0, tid);

    float d[4][4][4];
#pragma unroll
    for (int mt = 0; mt < 4; mt++)
#pragma unroll
        for (int nt = 0; nt < 4; nt++)
#pragma unroll
            for (int q = 0; q < 4; q++) d[mt][nt][q] = 0.f;

    // ---- main loop: 36 K-chunks of 64 ----
    for (int ch = 0; ch < 36; ch++) {
        asm volatile("cp.async.wait_group 0;" ::: "memory");
        __syncthreads();

        uint32_t wbase = smb + OFF_W + (ch & 1) * WBUF;
        uint32_t sbase = smb + OFF_S + (ch & 1) * SBUF;

        if (ch + 1 < 36) {
            int nb2 = (ch + 1) & 1;
            load_W(smb + OFF_W + nb2 * WBUF, ch + 1, tid);
            asm volatile("cp.async.commit_group;" ::: "memory");
            produce_S(sm + OFF_S + nb2 * SBUF, xhb, tabi, tabw, ch + 1, tid);
        }

#pragma unroll
        for (int kk = 0; kk < 4; kk++) {
            uint32_t bh[4][2];
#pragma unroll
            for (int nt = 0; nt < 4; nt++) {
                uint32_t baddr = sbase + (wn * 32 + nt * 8 + (lane & 7)) * RSTRIDE
                               + (kk * 16 + ((lane >> 3) & 1) * 8) * 2;
                ldsm2(bh[nt], baddr);
            }
#pragma unroll
            for (int mt = 0; mt < 4; mt++) {
                uint32_t aaddr = wbase + (wm * 64 + mt * 16 + (lane & 15)) * RSTRIDE
                               + (kk * 16 + (lane >> 4) * 8) * 2;
                uint32_t ah[4];
                ldsm4(ah, aaddr);
#pragma unroll
                for (int nt = 0; nt < 4; nt++)
                    mma16816(d[mt][nt], ah, bh[nt]);
            }
        }
    }

    // ---- epilogue: store accumulators ----
    int g4 = lane >> 2;
    int t4 = lane & 3;
#pragma unroll
    for (int mt = 0; mt < 4; mt++) {
#pragma unroll
        for (int nt = 0; nt < 4; nt++) {
            int pixb = wn * 32 + nt * 8 + t4 * 2;
            int h = h0 + (pixb >> 6);
            int w = pixb & 63;
            int oc0 = wm * 64 + mt * 16 + g4;
            float* p0 = out + ((size_t)b << 20) + ((size_t)oc0 << 12) + (h << 6) + w;
            *(float2*)p0 = make_float2(d[mt][nt][0], d[mt][nt][1]);
            float* p1 = p0 + (8 << 12);   // oc0 + 8
            *(float2*)p1 = make_float2(d[mt][nt][2], d[mt][nt][3]);
        }
    }
}

// ---------------------------------------------------------------------------
extern "C" void kernel_launch(void* const* d_in, const int* in_sizes, int n_in,
                              void* d_out, int out_size) {
    const float* x  = (const float*)d_in[0];
    const float* pw = (const float*)d_in[1];
    const float* pb = (const float*)d_in[2];
    const float* cw = (const float*)d_in[3];
    float* out = (float*)d_out;

    cudaFuncSetAttribute(k_main, cudaFuncAttributeMaxDynamicSharedMemorySize, SMEM_SZ);

    k_prep<<<KTOT, 256>>>(cw);
    k_prep2<<<NB * 256 * CH_WORDS / 256, 256>>>(x);
    k_offset<<<NB * NH, 256>>>(x, pw, pb);
    k_main<<<128, 512, SMEM_SZ>>>(out);
}